// round 9
// baseline (speedup 1.0000x reference)
#include <cuda_runtime.h>
#include <cuda_bf16.h>
#include <cstdint>

// ---------------- problem constants ----------------
#define BATCH   128
#define DCH     128
#define HW      1024
#define NROWS   131072
#define KCODE   256
#define TILE    128
#define NTILES  1024

// ---------------- output layout --------------------
#define Q_OFF      0
#define IDX_OFF    16777216
#define COMMIT_OFF 16908288
#define CBL_OFF    16908289
#define NCB_OFF    16908290
#define CNT_OFF    16941058
#define NW_OFF     16941314

// ---------------- device scratch -------------------
__device__ int   g_idx[NROWS];
__device__ float g_cnorm[KCODE];
__device__ float g_losspart[NTILES];
__device__ float g_part[BATCH * KCODE * DCH];
__device__ float g_part2[8 * KCODE * DCH];
__device__ float g_cntpart[BATCH * KCODE];
__device__ float g_snorm[KCODE];

// ---------------- SMEM layout (bytes) ----------------------
// bf16 phase: ZH[128][136] @0, ZL @34816, CH[256][136] @69632, CL @139264
// fp32 phase (aliased): zt[128][129] @0 (66048B), cbt[128][257] @69632 (131584B)
// small region @208896 (never aliased)
#define SA      136         // bf16 row stride (=68 words, 68%32==4 -> conflict-free frags)
#define ZH_B    0
#define ZL_B    34816
#define CH_B    69632
#define CL_B    139264
#define SCN_F   52224       // float index (208896/4)
#define SZN_F   52480
#define MINQ_F  52608       // [128][4]
#define SRMIN_F 53120
#define CCNT_I  53248       // [128]
#define CANDK_I 53376       // [128][12]
#define SIDX_I  54912       // [128]
#define SMEM_TC 220160

#define CBT_F   17408       // float idx of cbt (69632/4), stride 257
#define MARGIN  1.5e-4f

// ---------------- mma.sync helper (baseline PTX, works on sm_103) ----------
__device__ __forceinline__ void mma16816(float* d, const uint32_t* a,
                                         const uint32_t* b) {
    asm volatile(
        "mma.sync.aligned.m16n8k16.row.col.f32.bf16.bf16.f32 "
        "{%0,%1,%2,%3}, {%4,%5,%6,%7}, {%8,%9}, {%0,%1,%2,%3};"
        : "+f"(d[0]), "+f"(d[1]), "+f"(d[2]), "+f"(d[3])
        : "r"(a[0]), "r"(a[1]), "r"(a[2]), "r"(a[3]), "r"(b[0]), "r"(b[1]));
}

// ---------------- kernel 1: codebook row norms -----
__global__ void k_prep(const float* __restrict__ cb) {
    int w = threadIdx.x >> 5, lane = threadIdx.x & 31;
    for (int rr = 0; rr < 32; rr++) {
        int k = w * 32 + rr;
        float v0 = cb[k * DCH + lane];
        float s  = __fmul_rn(v0, v0);
#pragma unroll
        for (int j = 1; j < 4; j++) {
            float v = cb[k * DCH + j * 32 + lane];
            s = __fadd_rn(s, __fmul_rn(v, v));
        }
#pragma unroll
        for (int o = 16; o; o >>= 1)
            s = __fadd_rn(s, __shfl_xor_sync(0xffffffffu, s, o));
        if (lane == 0) g_cnorm[k] = s;
    }
}

// ---------------- kernel 2: HMMA distance + candidates + exact re-rank ----
__global__ void __launch_bounds__(512, 1)
k_gemm_mma(const float* __restrict__ z, const float* __restrict__ cb,
           float* __restrict__ out) {
    extern __shared__ float sm[];
    char* smc = (char*)sm;

    float* scn   = sm + SCN_F;
    float* szn   = sm + SZN_F;
    float* minq  = sm + MINQ_F;
    float* srmin = sm + SRMIN_F;
    int*   ccnt  = (int*)(sm + CCNT_I);
    int*   candk = (int*)(sm + CANDK_I);
    int*   sidx  = (int*)(sm + SIDX_I);
    __shared__ float red[16];

    const int tid    = threadIdx.x;
    const int w      = tid >> 5;
    const int l      = tid & 31;
    const int tileId = blockIdx.x;
    const int b      = tileId >> 3;
    const int hw0    = (tileId & 7) << 7;
    const int n0     = tileId * TILE;

    if (tid < 256) scn[tid] = g_cnorm[tid];
    if (tid < 128) ccnt[tid] = 0;

    // ---- stage z hi/lo bf16 [n][c], conflict-free pattern ----
    const float* zb = z + (b * DCH) * HW + hw0;
    {
        __nv_bfloat16* zh = (__nv_bfloat16*)(smc + ZH_B);
        __nv_bfloat16* zl = (__nv_bfloat16*)(smc + ZL_B);
        for (int it = 0; it < 16; it++) {
            int id = it * 512 + tid;
            int n  = ((id >> 2) & 7) | (((id >> 5) & 15) << 3);
            int cp = (id & 3) | ((id >> 9) << 2);
            int c  = cp * 2;
            float f0 = zb[c * HW + n], f1 = zb[(c + 1) * HW + n];
            __nv_bfloat16 h0 = __float2bfloat16_rn(f0);
            __nv_bfloat16 h1 = __float2bfloat16_rn(f1);
            __nv_bfloat16 l0 = __float2bfloat16_rn(f0 - __bfloat162float(h0));
            __nv_bfloat16 l1 = __float2bfloat16_rn(f1 - __bfloat162float(h1));
            *(uint32_t*)(zh + n * SA + c) =
                (uint32_t)__bfloat16_as_ushort(h0) |
                ((uint32_t)__bfloat16_as_ushort(h1) << 16);
            *(uint32_t*)(zl + n * SA + c) =
                (uint32_t)__bfloat16_as_ushort(l0) |
                ((uint32_t)__bfloat16_as_ushort(l1) << 16);
        }
    }
    // ---- stage codebook hi/lo bf16 [k][c] ----
    {
        __nv_bfloat16* ch = (__nv_bfloat16*)(smc + CH_B);
        __nv_bfloat16* cl = (__nv_bfloat16*)(smc + CL_B);
        for (int it = 0; it < 32; it++) {
            int id = it * 512 + tid;
            int k  = (id & 3) | ((id >> 8) << 2);
            int cp = ((id >> 2) & 7) | (((id >> 5) & 7) << 3);
            float2 f = *(const float2*)(cb + k * DCH + cp * 2);
            __nv_bfloat16 h0 = __float2bfloat16_rn(f.x);
            __nv_bfloat16 h1 = __float2bfloat16_rn(f.y);
            __nv_bfloat16 l0 = __float2bfloat16_rn(f.x - __bfloat162float(h0));
            __nv_bfloat16 l1 = __float2bfloat16_rn(f.y - __bfloat162float(h1));
            *(uint32_t*)(ch + k * SA + cp * 2) =
                (uint32_t)__bfloat16_as_ushort(h0) |
                ((uint32_t)__bfloat16_as_ushort(h1) << 16);
            *(uint32_t*)(cl + k * SA + cp * 2) =
                (uint32_t)__bfloat16_as_ushort(l0) |
                ((uint32_t)__bfloat16_as_ushort(l1) << 16);
        }
    }
    __syncthreads();

    // ---- HMMA mainloop: 3 terms (zh*ch + zh*cl + zl*ch) ----
    const int mg = w & 3, q = w >> 2;
    const int mbase = mg * 32, nbase = q * 64;
    const int r4 = l >> 2, c4 = l & 3;

    float acc[64];
#pragma unroll
    for (int i = 0; i < 64; i++) acc[i] = 0.f;

    const uint32_t* zhw = (const uint32_t*)(smc + ZH_B);
    const uint32_t* zlw = (const uint32_t*)(smc + ZL_B);
    const uint32_t* chw = (const uint32_t*)(smc + CH_B);
    const uint32_t* clw = (const uint32_t*)(smc + CL_B);

#pragma unroll
    for (int kt = 0; kt < 8; kt++) {
        const int ko = kt * 8 + c4;     // word offset within a row
        uint32_t ah[8], al_[8];
#pragma unroll
        for (int mt = 0; mt < 2; mt++) {
            int r0 = (mbase + mt * 16 + r4) * 68;
            ah[mt*4+0] = zhw[r0 + ko];
            ah[mt*4+1] = zhw[r0 + 8*68 + ko];
            ah[mt*4+2] = zhw[r0 + ko + 4];
            ah[mt*4+3] = zhw[r0 + 8*68 + ko + 4];
            al_[mt*4+0] = zlw[r0 + ko];
            al_[mt*4+1] = zlw[r0 + 8*68 + ko];
            al_[mt*4+2] = zlw[r0 + ko + 4];
            al_[mt*4+3] = zlw[r0 + 8*68 + ko + 4];
        }
#pragma unroll
        for (int nt = 0; nt < 8; nt++) {
            int kb = (nbase + nt * 8 + r4) * 68;
            uint32_t bh[2], bl_[2];
            bh[0]  = chw[kb + ko];  bh[1]  = chw[kb + ko + 4];
            bl_[0] = clw[kb + ko];  bl_[1] = clw[kb + ko + 4];
            mma16816(acc + nt*4,      ah,     bh);
            mma16816(acc + 32 + nt*4, ah + 4, bh);
            mma16816(acc + nt*4,      ah,     bl_);
            mma16816(acc + 32 + nt*4, ah + 4, bl_);
            mma16816(acc + nt*4,      al_,    bh);
            mma16816(acc + 32 + nt*4, al_ + 4, bh);
        }
    }

    // ---- pass 1: per-row min of approx distance (registers -> shfl -> smem)
#pragma unroll
    for (int s = 0; s < 4; s++) {
        int mt = s >> 1, hf = s & 1;
        float m = 3.4e38f;
#pragma unroll
        for (int nt = 0; nt < 8; nt++)
#pragma unroll
            for (int j = 0; j < 2; j++) {
                int k = nbase + nt * 8 + c4 * 2 + j;
                float d = scn[k] - 2.f * acc[mt*32 + nt*4 + hf*2 + j];
                m = fminf(m, d);
            }
        m = fminf(m, __shfl_xor_sync(0xffffffffu, m, 1));
        m = fminf(m, __shfl_xor_sync(0xffffffffu, m, 2));
        if (c4 == 0) {
            int row = mbase + mt * 16 + hf * 8 + r4;
            minq[row * 4 + q] = m;
        }
    }
    __syncthreads();
    if (tid < 128)
        srmin[tid] = fminf(fminf(minq[tid*4], minq[tid*4+1]),
                           fminf(minq[tid*4+2], minq[tid*4+3]));
    __syncthreads();

    // ---- pass 2: collect candidates within margin ----
#pragma unroll
    for (int s = 0; s < 4; s++) {
        int mt = s >> 1, hf = s & 1;
        int row = mbase + mt * 16 + hf * 8 + r4;
        float thr = srmin[row] + MARGIN;
#pragma unroll
        for (int nt = 0; nt < 8; nt++)
#pragma unroll
            for (int j = 0; j < 2; j++) {
                int k = nbase + nt * 8 + c4 * 2 + j;
                float d = scn[k] - 2.f * acc[mt*32 + nt*4 + hf*2 + j];
                if (d <= thr) {
                    int p = atomicAdd(&ccnt[row], 1);
                    if (p < 12) candk[row * 12 + p] = k;
                }
            }
    }
    __syncthreads();

    // ---- restage fp32 zt / cbt (aliases bf16 regions) ----
    float* zt  = sm;              // [128 c][129]
    float* cbt = sm + CBT_F;      // [128 c][257]
    for (int i = tid; i < TILE * DCH; i += 512) {
        int c = i >> 7, n = i & 127;
        zt[c * 129 + n] = zb[c * HW + n];
    }
    for (int i = tid; i < KCODE * DCH; i += 512) {
        int k = i >> 7, c = i & 127;
        cbt[c * 257 + k] = cb[k * DCH + c];
    }
    __syncthreads();

    // ---- znorm per row (XLA pattern, identical rounding to passing R7) ----
    for (int r = 0; r < 8; r++) {
        int n = w * 8 + r;
        float v0 = zt[l * 129 + n];
        float a  = __fmul_rn(v0, v0);
#pragma unroll
        for (int j = 1; j < 4; j++) {
            float v = zt[(l + 32 * j) * 129 + n];
            a = __fadd_rn(a, __fmul_rn(v, v));
        }
#pragma unroll
        for (int o = 16; o; o >>= 1)
            a = __fadd_rn(a, __shfl_xor_sync(0xffffffffu, a, o));
        if (l == 0) szn[n] = a;
    }
    __syncthreads();

    // ---- exact re-rank (reference-rounded sequential FFMA) ----
    for (int it = 0; it < 8; it++) {
        int r  = 8 * w + it;
        int cn = min(ccnt[r], 12);
        bool act = l < cn;
        int k = act ? candk[r * 12 + l] : 0x7fffffff;
        float d = 3.4e38f;
        if (act) {
            float a = 0.f;
            const float* cr = cbt + k;
#pragma unroll 8
            for (int c = 0; c < DCH; c++)
                a = __fmaf_rn(zt[c * 129 + r], cr[c * 257], a);
            d = __fadd_rn(__fadd_rn(szn[r], -__fmul_rn(2.f, a)), scn[k]);
        }
#pragma unroll
        for (int off = 16; off; off >>= 1) {
            float ov = __shfl_xor_sync(0xffffffffu, d, off);
            int   ok = __shfl_xor_sync(0xffffffffu, k, off);
            if (ov < d || (ov == d && ok < k)) { d = ov; k = ok; }
        }
        if (l == 0) {
            sidx[r] = k;
            g_idx[n0 + r] = k;
            out[IDX_OFF + n0 + r] = (float)k;
        }
    }
    __syncthreads();

    // ---- quantize (straight-through) + loss ----
    float lsum = 0.f;
    float* outq = out + Q_OFF + (b * DCH) * HW + hw0;
#pragma unroll 4
    for (int it = 0; it < 32; it++) {
        int e = it * 512 + tid;
        int c = e >> 7, n = e & 127;
        int k = sidx[n];
        float zv = zt[c * 129 + n];
        float qv = cbt[c * 257 + k];
        float d  = __fadd_rn(qv, -zv);
        outq[c * HW + n] = __fadd_rn(zv, d);
        lsum += d * d;
    }
#pragma unroll
    for (int off = 16; off; off >>= 1)
        lsum += __shfl_xor_sync(0xffffffffu, lsum, off);
    if (l == 0) red[w] = lsum;
    __syncthreads();
    if (tid == 0) {
        float t = 0.f;
        for (int i = 0; i < 16; i++) t += red[i];
        g_losspart[blockIdx.x] = t;
    }
}

// ---------------- kernel 3: per-batch enc_batch via staged SMEM -----------
#define CHUNK 64
__global__ void __launch_bounds__(512, 1)
k_encbatch(const float* __restrict__ z) {
    extern __shared__ float sm[];
    float* sacc  = sm;                              // [256][128]
    float* zs    = sm + KCODE * DCH;                // [128][65]
    int*   ssidx = (int*)(zs + 128 * 65);           // [1024]
    int*   scnt  = ssidx + HW;                      // [256]
    const int tid = threadIdx.x, b = blockIdx.x;

    for (int i = tid; i < KCODE * DCH; i += 512) sacc[i] = 0.f;
    if (tid < 256) scnt[tid] = 0;
    for (int i = tid; i < HW; i += 512) ssidx[i] = g_idx[b * HW + i];

    const int ks = tid >> 7, c = tid & 127;
    const float* zb = z + (b * DCH) * HW;

    for (int ch = 0; ch < HW / CHUNK; ch++) {
        const int r0 = ch * CHUNK;
        __syncthreads();
        for (int i = tid; i < DCH * CHUNK; i += 512) {
            int cc = i >> 6, r = i & (CHUNK - 1);
            zs[cc * (CHUNK + 1) + r] = zb[cc * HW + r0 + r];
        }
        __syncthreads();
#pragma unroll 4
        for (int r = 0; r < CHUNK; r++) {
            int k = ssidx[r0 + r];
            if ((k & 3) == ks) {
                sacc[k * DCH + c] += zs[c * (CHUNK + 1) + r];
                if (c == 0) scnt[k]++;
            }
        }
    }
    __syncthreads();
    for (int i = tid; i < KCODE * DCH; i += 512)
        g_part[b * (KCODE * DCH) + i] = sacc[i];
    if (tid < 256) g_cntpart[b * KCODE + tid] = (float)scnt[tid];
}

// ---------------- kernel 4a/4b: batch reduction ---------------------------
__global__ void k_reduceA() {
    int bg = blockIdx.x >> 8;
    int k  = blockIdx.x & 255;
    int c  = threadIdx.x;
    const float* p = g_part + (bg * 16) * (KCODE * DCH) + k * DCH + c;
    float s = 0.f;
#pragma unroll
    for (int bi = 0; bi < 16; bi++) s += p[bi * (KCODE * DCH)];
    g_part2[bg * (KCODE * DCH) + k * DCH + c] = s;
}
__global__ void k_reduceB(const float* __restrict__ emaw,
                          float* __restrict__ out) {
    int k = blockIdx.x, c = threadIdx.x;
    float s = 0.f;
#pragma unroll
    for (int bg = 0; bg < 8; bg++) s += g_part2[bg * (KCODE * DCH) + k * DCH + c];
    int i = k * DCH + c;
    out[NW_OFF + i] = __fadd_rn(__fmul_rn(0.99f, emaw[i]), __fmul_rn(0.01f, s));
}

// ---------------- kernel 5: counts, losses, snorm -------------------------
__global__ void k_final(const float* __restrict__ emac, float* __restrict__ out) {
    __shared__ float snc[256], sred[256];
    __shared__ float s_n;
    const int t = threadIdx.x;

    float cs = 0.f;
#pragma unroll 8
    for (int b = 0; b < BATCH; b++) cs += g_cntpart[b * KCODE + t];
    float nc = __fadd_rn(__fmul_rn(0.99f, emac[t]), __fmul_rn(0.01f, cs));
    out[CNT_OFF + t] = nc;
    snc[t] = nc;

    float lp = 0.f;
    for (int i = t; i < NTILES; i += 256) lp += g_losspart[i];
    sred[t] = lp;
    __syncthreads();

    if (t == 0) {
        float n = 0.f;
        for (int i = 0; i < 256; i++) n += snc[i];
        s_n = n;
        float L = 0.f;
        for (int i = 0; i < 256; i++) L += sred[i];
        L /= 16777216.0f;
        out[COMMIT_OFF] = 0.25f * L;
        out[CBL_OFF]    = L;
    }
    __syncthreads();

    float n = s_n;
    g_snorm[t] = __fmul_rn(__fdiv_rn(__fadd_rn(snc[t], 1e-5f),
                                     __fadd_rn(n, 256.0f * 1e-5f)), n);
}

// ---------------- kernel 6: new_codebook ----------------------------------
__global__ void k_ncb(float* __restrict__ out) {
    int k = blockIdx.x, c = threadIdx.x;
    int i = k * DCH + c;
    out[NCB_OFF + i] = __fdiv_rn(out[NW_OFF + i], g_snorm[k]);
}

// ---------------- launch ---------------------------------------------------
extern "C" void kernel_launch(void* const* d_in, const int* in_sizes, int n_in,
                              void* d_out, int out_size) {
    const float* z    = (const float*)d_in[0];
    const float* cb   = (const float*)d_in[1];
    const float* emac = (const float*)d_in[2];
    const float* emaw = (const float*)d_in[3];
    float* out = (float*)d_out;

    const int ENC_SMEM = (KCODE * DCH + 128 * 65) * 4 + (HW + KCODE) * 4;
    cudaFuncSetAttribute(k_gemm_mma, cudaFuncAttributeMaxDynamicSharedMemorySize,
                         SMEM_TC);
    cudaFuncSetAttribute(k_encbatch, cudaFuncAttributeMaxDynamicSharedMemorySize,
                         ENC_SMEM);

    k_prep<<<1, 256>>>(cb);
    k_gemm_mma<<<NTILES, 512, SMEM_TC>>>(z, cb, out);
    k_encbatch<<<BATCH, 512, ENC_SMEM>>>(z);
    k_reduceA<<<2048, 128>>>();
    k_reduceB<<<KCODE, DCH>>>(emaw, out);
    k_final<<<1, 256>>>(emac, out);
    k_ncb<<<KCODE, DCH>>>(out);
}

// round 11
// speedup vs baseline: 1.3300x; 1.3300x over previous
#include <cuda_runtime.h>
#include <cuda_bf16.h>
#include <cstdint>

// ---------------- problem constants ----------------
#define BATCH   128
#define DCH     128
#define HW      1024
#define NROWS   131072
#define KCODE   256
#define TILE    128
#define NTILES  1024

// ---------------- output layout --------------------
#define Q_OFF      0
#define IDX_OFF    16777216
#define COMMIT_OFF 16908288
#define CBL_OFF    16908289
#define NCB_OFF    16908290
#define CNT_OFF    16941058
#define NW_OFF     16941314

// ---------------- device scratch -------------------
__device__ int   g_idx[NROWS];
__device__ float g_cnorm[KCODE];
__device__ float g_losspart[NTILES];
__device__ float g_part[BATCH * KCODE * DCH];
__device__ float g_part2[8 * KCODE * DCH];
__device__ float g_cntpart[BATCH * KCODE];
__device__ float g_snorm[KCODE];

// ---------------- SMEM layout (bytes) ----------------------
// bf16 phase: ZH[128][136B] @0, ZL @34816, CH[256][136B] @69632, CL @139264
// fp32 phase (aliased): zt[128][129] @0, cbt[128][257] @69632
// small region @208896 (never aliased)
#define SA      136
#define ZH_B    0
#define ZL_B    34816
#define CH_B    69632
#define CL_B    139264
#define SCN_F   52224
#define SZN_F   52480
#define MINQ_F  52608       // [128][4]
#define SRMIN_F 53120
#define CCNT_I  53248       // [128]
#define CANDK_I 53376       // [128][12]
#define SIDX_I  54912       // [128]
#define SD_F    55040       // [128][12]
#define SMEM_TC 226304

#define CBT_F   17408       // float idx of cbt, stride 257
#define MARGIN  1.5e-4f

// ---------------- mma.sync helper ------------------------------------------
__device__ __forceinline__ void mma16816(float* d, const uint32_t* a,
                                         const uint32_t* b) {
    asm volatile(
        "mma.sync.aligned.m16n8k16.row.col.f32.bf16.bf16.f32 "
        "{%0,%1,%2,%3}, {%4,%5,%6,%7}, {%8,%9}, {%0,%1,%2,%3};"
        : "+f"(d[0]), "+f"(d[1]), "+f"(d[2]), "+f"(d[3])
        : "r"(a[0]), "r"(a[1]), "r"(a[2]), "r"(a[3]), "r"(b[0]), "r"(b[1]));
}

// ---------------- dummy kernels (ncu capture-slot steering) ----------------
__global__ void k_dummy1() { if (threadIdx.x < 64) g_losspart[threadIdx.x] = 0.f; }
__global__ void k_dummy2() { if (threadIdx.x < 64) g_snorm[threadIdx.x] = 0.f; }

// ---------------- kernel: codebook row norms -------------------------------
__global__ void k_prep(const float* __restrict__ cb) {
    int w = threadIdx.x >> 5, lane = threadIdx.x & 31;
    for (int rr = 0; rr < 32; rr++) {
        int k = w * 32 + rr;
        float v0 = cb[k * DCH + lane];
        float s  = __fmul_rn(v0, v0);
#pragma unroll
        for (int j = 1; j < 4; j++) {
            float v = cb[k * DCH + j * 32 + lane];
            s = __fadd_rn(s, __fmul_rn(v, v));
        }
#pragma unroll
        for (int o = 16; o; o >>= 1)
            s = __fadd_rn(s, __shfl_xor_sync(0xffffffffu, s, o));
        if (lane == 0) g_cnorm[k] = s;
    }
}

// ---------------- kernel: HMMA distance + candidates + exact re-rank -------
__global__ void __launch_bounds__(512, 1)
k_gemm_mma(const float* __restrict__ z, const float* __restrict__ cb,
           float* __restrict__ out) {
    extern __shared__ float sm[];
    char* smc = (char*)sm;

    float* scn   = sm + SCN_F;
    float* szn   = sm + SZN_F;
    float* minq  = sm + MINQ_F;
    float* srmin = sm + SRMIN_F;
    int*   ccnt  = (int*)(sm + CCNT_I);
    int*   candk = (int*)(sm + CANDK_I);
    int*   sidx  = (int*)(sm + SIDX_I);
    float* sd    = sm + SD_F;
    __shared__ float red[16];

    const int tid    = threadIdx.x;
    const int w      = tid >> 5;
    const int l      = tid & 31;
    const int tileId = blockIdx.x;
    const int b      = tileId >> 3;
    const int hw0    = (tileId & 7) << 7;
    const int n0     = tileId * TILE;

    if (tid < 256) scn[tid] = g_cnorm[tid];
    if (tid < 128) ccnt[tid] = 0;

    // ---- stage z hi/lo bf16 [n][c-pair], coalesced global reads ----
    const float* zb = z + (b * DCH) * HW + hw0;
    {
        uint32_t* zh = (uint32_t*)(smc + ZH_B);
        uint32_t* zl = (uint32_t*)(smc + ZL_B);
#pragma unroll
        for (int it = 0; it < 16; it++) {
            int id = it * 512 + tid;
            int n  = id & 127, p = id >> 7, c = p * 2;
            float f0 = zb[c * HW + n], f1 = zb[(c + 1) * HW + n];
            __nv_bfloat16 h0 = __float2bfloat16_rn(f0);
            __nv_bfloat16 h1 = __float2bfloat16_rn(f1);
            __nv_bfloat16 l0 = __float2bfloat16_rn(f0 - __bfloat162float(h0));
            __nv_bfloat16 l1 = __float2bfloat16_rn(f1 - __bfloat162float(h1));
            zh[n * 68 + p] = (uint32_t)__bfloat16_as_ushort(h0) |
                             ((uint32_t)__bfloat16_as_ushort(h1) << 16);
            zl[n * 68 + p] = (uint32_t)__bfloat16_as_ushort(l0) |
                             ((uint32_t)__bfloat16_as_ushort(l1) << 16);
        }
    }
    // ---- stage codebook hi/lo bf16 [k][c-pair], coalesced ----
    {
        uint32_t* ch = (uint32_t*)(smc + CH_B);
        uint32_t* cl = (uint32_t*)(smc + CL_B);
#pragma unroll
        for (int it = 0; it < 32; it++) {
            int id = it * 512 + tid;
            int p  = id & 63, k = id >> 6;
            float2 f = *(const float2*)(cb + k * DCH + p * 2);
            __nv_bfloat16 h0 = __float2bfloat16_rn(f.x);
            __nv_bfloat16 h1 = __float2bfloat16_rn(f.y);
            __nv_bfloat16 l0 = __float2bfloat16_rn(f.x - __bfloat162float(h0));
            __nv_bfloat16 l1 = __float2bfloat16_rn(f.y - __bfloat162float(h1));
            ch[k * 68 + p] = (uint32_t)__bfloat16_as_ushort(h0) |
                             ((uint32_t)__bfloat16_as_ushort(h1) << 16);
            cl[k * 68 + p] = (uint32_t)__bfloat16_as_ushort(l0) |
                             ((uint32_t)__bfloat16_as_ushort(l1) << 16);
        }
    }
    __syncthreads();

    // ---- HMMA mainloop: 3 terms (zh*ch + zh*cl + zl*ch) ----
    const int mg = w & 3, q = w >> 2;
    const int mbase = mg * 32, nbase = q * 64;
    const int r4 = l >> 2, c4 = l & 3;

    float acc[64];
#pragma unroll
    for (int i = 0; i < 64; i++) acc[i] = 0.f;

    const uint32_t* zhw = (const uint32_t*)(smc + ZH_B);
    const uint32_t* zlw = (const uint32_t*)(smc + ZL_B);
    const uint32_t* chw = (const uint32_t*)(smc + CH_B);
    const uint32_t* clw = (const uint32_t*)(smc + CL_B);

#pragma unroll
    for (int kt = 0; kt < 8; kt++) {
        const int ko = kt * 8 + c4;
        uint32_t ah[8], al_[8];
#pragma unroll
        for (int mt = 0; mt < 2; mt++) {
            int r0 = (mbase + mt * 16 + r4) * 68;
            ah[mt*4+0] = zhw[r0 + ko];
            ah[mt*4+1] = zhw[r0 + 8*68 + ko];
            ah[mt*4+2] = zhw[r0 + ko + 4];
            ah[mt*4+3] = zhw[r0 + 8*68 + ko + 4];
            al_[mt*4+0] = zlw[r0 + ko];
            al_[mt*4+1] = zlw[r0 + 8*68 + ko];
            al_[mt*4+2] = zlw[r0 + ko + 4];
            al_[mt*4+3] = zlw[r0 + 8*68 + ko + 4];
        }
#pragma unroll
        for (int nt = 0; nt < 8; nt++) {
            int kb = (nbase + nt * 8 + r4) * 68;
            uint32_t bh[2], bl_[2];
            bh[0]  = chw[kb + ko];  bh[1]  = chw[kb + ko + 4];
            bl_[0] = clw[kb + ko];  bl_[1] = clw[kb + ko + 4];
            mma16816(acc + nt*4,      ah,      bh);
            mma16816(acc + 32 + nt*4, ah + 4,  bh);
            mma16816(acc + nt*4,      ah,      bl_);
            mma16816(acc + 32 + nt*4, ah + 4,  bl_);
            mma16816(acc + nt*4,      al_,     bh);
            mma16816(acc + 32 + nt*4, al_ + 4, bh);
        }
    }

    // ---- pass 1: per-row min of approx distance ----
#pragma unroll
    for (int s = 0; s < 4; s++) {
        int mt = s >> 1, hf = s & 1;
        float m = 3.4e38f;
#pragma unroll
        for (int nt = 0; nt < 8; nt++)
#pragma unroll
            for (int j = 0; j < 2; j++) {
                int k = nbase + nt * 8 + c4 * 2 + j;
                float d = scn[k] - 2.f * acc[mt*32 + nt*4 + hf*2 + j];
                m = fminf(m, d);
            }
        m = fminf(m, __shfl_xor_sync(0xffffffffu, m, 1));
        m = fminf(m, __shfl_xor_sync(0xffffffffu, m, 2));
        if (c4 == 0) {
            int row = mbase + mt * 16 + hf * 8 + r4;
            minq[row * 4 + q] = m;
        }
    }
    __syncthreads();
    if (tid < 128)
        srmin[tid] = fminf(fminf(minq[tid*4], minq[tid*4+1]),
                           fminf(minq[tid*4+2], minq[tid*4+3]));
    __syncthreads();

    // ---- pass 2: collect candidates within margin ----
#pragma unroll
    for (int s = 0; s < 4; s++) {
        int mt = s >> 1, hf = s & 1;
        int row = mbase + mt * 16 + hf * 8 + r4;
        float thr = srmin[row] + MARGIN;
#pragma unroll
        for (int nt = 0; nt < 8; nt++)
#pragma unroll
            for (int j = 0; j < 2; j++) {
                int k = nbase + nt * 8 + c4 * 2 + j;
                float d = scn[k] - 2.f * acc[mt*32 + nt*4 + hf*2 + j];
                if (d <= thr) {
                    int p = atomicAdd(&ccnt[row], 1);
                    if (p < 12) candk[row * 12 + p] = k;
                }
            }
    }
    __syncthreads();

    // ---- restage fp32 zt / cbt (aliases bf16 regions) ----
    float* zt  = sm;              // [128 c][129]
    float* cbt = sm + CBT_F;      // [128 c][257]
    for (int i = tid; i < TILE * DCH; i += 512) {
        int c = i >> 7, n = i & 127;
        zt[c * 129 + n] = zb[c * HW + n];
    }
    for (int i = tid; i < KCODE * DCH; i += 512) {
        int k = i >> 7, c = i & 127;
        cbt[c * 257 + k] = cb[k * DCH + c];
    }
    __syncthreads();

    // ---- znorm per row (XLA pattern, identical rounding) ----
    for (int r = 0; r < 8; r++) {
        int n = w * 8 + r;
        float v0 = zt[l * 129 + n];
        float a  = __fmul_rn(v0, v0);
#pragma unroll
        for (int j = 1; j < 4; j++) {
            float v = zt[(l + 32 * j) * 129 + n];
            a = __fadd_rn(a, __fmul_rn(v, v));
        }
#pragma unroll
        for (int o = 16; o; o >>= 1)
            a = __fadd_rn(a, __shfl_xor_sync(0xffffffffu, a, o));
        if (l == 0) szn[n] = a;
    }
    __syncthreads();

    // ---- exact re-rank: one candidate per thread (reference-rounded) ----
    {
        // pass A: slots j = 0..3
        int row = tid >> 2, j = tid & 3;
        int cn = min(ccnt[row], 12);
        float d = 3.4e38f;
        if (j < cn) {
            int k = candk[row * 12 + j];
            float a = 0.f;
            const float* cr = cbt + k;
#pragma unroll 8
            for (int c = 0; c < DCH; c++)
                a = __fmaf_rn(zt[c * 129 + row], cr[c * 257], a);
            d = __fadd_rn(__fadd_rn(szn[row], -__fmul_rn(2.f, a)), scn[k]);
        }
        sd[row * 12 + j] = d;
        // pass B: slots j = 4..11 (rare)
#pragma unroll
        for (int it = 0; it < 2; it++) {
            int id = it * 512 + tid;
            int row2 = id >> 3, j2 = 4 + (id & 7);
            int cn2 = min(ccnt[row2], 12);
            float d2 = 3.4e38f;
            if (j2 < cn2) {
                int k = candk[row2 * 12 + j2];
                float a = 0.f;
                const float* cr = cbt + k;
#pragma unroll 8
                for (int c = 0; c < DCH; c++)
                    a = __fmaf_rn(zt[c * 129 + row2], cr[c * 257], a);
                d2 = __fadd_rn(__fadd_rn(szn[row2], -__fmul_rn(2.f, a)), scn[k]);
            }
            sd[row2 * 12 + j2] = d2;
        }
    }
    __syncthreads();

    // ---- per-row (d, k) min reduce: warp w handles rows 8w..8w+7 ----
    for (int i = 0; i < 8; i++) {
        int row = w * 8 + i;
        float d = (l < 12) ? sd[row * 12 + l] : 3.4e38f;
        int   k = (l < 12) ? candk[row * 12 + l] : 0x7fffffff;
        if (d >= 3.4e38f) k = 0x7fffffff;
#pragma unroll
        for (int off = 16; off; off >>= 1) {
            float ov = __shfl_xor_sync(0xffffffffu, d, off);
            int   ok = __shfl_xor_sync(0xffffffffu, k, off);
            if (ov < d || (ov == d && ok < k)) { d = ov; k = ok; }
        }
        if (l == 0) {
            sidx[row] = k;
            g_idx[n0 + row] = k;
            out[IDX_OFF + n0 + row] = (float)k;
        }
    }
    __syncthreads();

    // ---- quantize (straight-through) + loss ----
    float lsum = 0.f;
    float* outq = out + Q_OFF + (b * DCH) * HW + hw0;
#pragma unroll 4
    for (int it = 0; it < 32; it++) {
        int e = it * 512 + tid;
        int c = e >> 7, n = e & 127;
        int k = sidx[n];
        float zv = zt[c * 129 + n];
        float qv = cbt[c * 257 + k];
        float d  = __fadd_rn(qv, -zv);
        outq[c * HW + n] = __fadd_rn(zv, d);
        lsum += d * d;
    }
#pragma unroll
    for (int off = 16; off; off >>= 1)
        lsum += __shfl_xor_sync(0xffffffffu, lsum, off);
    if (l == 0) red[w] = lsum;
    __syncthreads();
    if (tid == 0) {
        float t = 0.f;
        for (int i = 0; i < 16; i++) t += red[i];
        g_losspart[blockIdx.x] = t;
    }
}

// ---------------- kernel: per-batch enc_batch via staged SMEM --------------
#define CHUNK 64
__global__ void __launch_bounds__(512, 1)
k_encbatch(const float* __restrict__ z) {
    extern __shared__ float sm[];
    float* sacc  = sm;                              // [256][128]
    float* zs    = sm + KCODE * DCH;                // [128][65]
    int*   ssidx = (int*)(zs + 128 * 65);           // [1024]
    int*   scnt  = ssidx + HW;                      // [256]
    const int tid = threadIdx.x, b = blockIdx.x;

    for (int i = tid; i < KCODE * DCH; i += 512) sacc[i] = 0.f;
    if (tid < 256) scnt[tid] = 0;
    for (int i = tid; i < HW; i += 512) ssidx[i] = g_idx[b * HW + i];

    const int ks = tid >> 7, c = tid & 127;
    const float* zb = z + (b * DCH) * HW;

    for (int ch = 0; ch < HW / CHUNK; ch++) {
        const int r0 = ch * CHUNK;
        __syncthreads();
        for (int i = tid; i < DCH * CHUNK; i += 512) {
            int cc = i >> 6, r = i & (CHUNK - 1);
            zs[cc * (CHUNK + 1) + r] = zb[cc * HW + r0 + r];
        }
        __syncthreads();
#pragma unroll 4
        for (int r = 0; r < CHUNK; r++) {
            int k = ssidx[r0 + r];
            if ((k & 3) == ks) {
                sacc[k * DCH + c] += zs[c * (CHUNK + 1) + r];
                if (c == 0) scnt[k]++;
            }
        }
    }
    __syncthreads();
    for (int i = tid; i < KCODE * DCH; i += 512)
        g_part[b * (KCODE * DCH) + i] = sacc[i];
    if (tid < 256) g_cntpart[b * KCODE + tid] = (float)scnt[tid];
}

// ---------------- batch reduction ------------------------------------------
__global__ void k_reduceA() {
    int bg = blockIdx.x >> 8;
    int k  = blockIdx.x & 255;
    int c  = threadIdx.x;
    const float* p = g_part + (bg * 16) * (KCODE * DCH) + k * DCH + c;
    float s = 0.f;
#pragma unroll
    for (int bi = 0; bi < 16; bi++) s += p[bi * (KCODE * DCH)];
    g_part2[bg * (KCODE * DCH) + k * DCH + c] = s;
}
__global__ void k_reduceB(const float* __restrict__ emaw,
                          float* __restrict__ out) {
    int k = blockIdx.x, c = threadIdx.x;
    float s = 0.f;
#pragma unroll
    for (int bg = 0; bg < 8; bg++) s += g_part2[bg * (KCODE * DCH) + k * DCH + c];
    int i = k * DCH + c;
    out[NW_OFF + i] = __fadd_rn(__fmul_rn(0.99f, emaw[i]), __fmul_rn(0.01f, s));
}

// ---------------- counts, losses, snorm ------------------------------------
__global__ void k_final(const float* __restrict__ emac, float* __restrict__ out) {
    __shared__ float snc[256], sred[256];
    __shared__ float s_n;
    const int t = threadIdx.x;

    float cs = 0.f;
#pragma unroll 8
    for (int b = 0; b < BATCH; b++) cs += g_cntpart[b * KCODE + t];
    float nc = __fadd_rn(__fmul_rn(0.99f, emac[t]), __fmul_rn(0.01f, cs));
    out[CNT_OFF + t] = nc;
    snc[t] = nc;

    float lp = 0.f;
    for (int i = t; i < NTILES; i += 256) lp += g_losspart[i];
    sred[t] = lp;
    __syncthreads();

    if (t == 0) {
        float n = 0.f;
        for (int i = 0; i < 256; i++) n += snc[i];
        s_n = n;
        float L = 0.f;
        for (int i = 0; i < 256; i++) L += sred[i];
        L /= 16777216.0f;
        out[COMMIT_OFF] = 0.25f * L;
        out[CBL_OFF]    = L;
    }
    __syncthreads();

    float n = s_n;
    g_snorm[t] = __fmul_rn(__fdiv_rn(__fadd_rn(snc[t], 1e-5f),
                                     __fadd_rn(n, 256.0f * 1e-5f)), n);
}

// ---------------- new_codebook ---------------------------------------------
__global__ void k_ncb(float* __restrict__ out) {
    int k = blockIdx.x, c = threadIdx.x;
    int i = k * DCH + c;
    out[NCB_OFF + i] = __fdiv_rn(out[NW_OFF + i], g_snorm[k]);
}

// ---------------- launch ---------------------------------------------------
extern "C" void kernel_launch(void* const* d_in, const int* in_sizes, int n_in,
                              void* d_out, int out_size) {
    const float* z    = (const float*)d_in[0];
    const float* cb   = (const float*)d_in[1];
    const float* emac = (const float*)d_in[2];
    const float* emaw = (const float*)d_in[3];
    float* out = (float*)d_out;

    const int ENC_SMEM = (KCODE * DCH + 128 * 65) * 4 + (HW + KCODE) * 4;
    cudaFuncSetAttribute(k_gemm_mma, cudaFuncAttributeMaxDynamicSharedMemorySize,
                         SMEM_TC);
    cudaFuncSetAttribute(k_encbatch, cudaFuncAttributeMaxDynamicSharedMemorySize,
                         ENC_SMEM);

    k_prep<<<1, 256>>>(cb);          // launch 0
    k_dummy1<<<1, 64>>>();           // launch 1
    k_dummy2<<<1, 64>>>();           // launch 2
    k_gemm_mma<<<NTILES, 512, SMEM_TC>>>(z, cb, out);   // launch 3 (ncu slot)
    k_encbatch<<<BATCH, 512, ENC_SMEM>>>(z);
    k_reduceA<<<2048, 128>>>();
    k_reduceB<<<KCODE, DCH>>>(emaw, out);
    k_final<<<1, 256>>>(emac, out);
    k_ncb<<<KCODE, DCH>>>(out);
}

// round 14
// speedup vs baseline: 1.5152x; 1.1393x over previous
#include <cuda_runtime.h>
#include <cuda_fp16.h>
#include <cstdint>

// ---------------- problem constants ----------------
#define BATCH   128
#define DCH     128
#define HW      1024
#define NROWS   131072
#define KCODE   256
#define TILE    128
#define NTILES  1024

// ---------------- output layout --------------------
#define Q_OFF      0
#define IDX_OFF    16777216
#define COMMIT_OFF 16908288
#define CBL_OFF    16908289
#define NCB_OFF    16908290
#define CNT_OFF    16941058
#define NW_OFF     16941314

// ---------------- device scratch -------------------
__device__ int   g_idx[NROWS];
__device__ float g_cnorm[KCODE];
__device__ float g_losspart[NTILES];
__device__ float g_part[BATCH * KCODE * DCH];
__device__ float g_part2[8 * KCODE * DCH];
__device__ float g_cntpart[BATCH * KCODE];
__device__ float g_snorm[KCODE];

// ---------------- SMEM layout (bytes) ----------------------
// fp16 phase: ZF[128 rows][272B stride] @0 (34816), CF[256][272B] @34816 (69632)
// fp32 phase (aliased): zt[128][129] @0 (66048), cbt[128][257] @69632 (131584)
// small region @208896 (never aliased)
#define ZF_B    0
#define CF_B    34816
#define SCN_F   52224       // float idx (208896/4)
#define SZN_F   52480
#define MINQ_F  52608       // [128][4]
#define SRMIN_F 53120
#define CCNT_I  53248       // [128]
#define CANDK_I 53376       // [128][12]
#define SIDX_I  54912       // [128]
#define SD_F    55040       // [128][12]
#define SMEM_TC 226304

#define CBT_F   17408       // float idx of cbt (69632/4), stride 257
#define MARGIN  8e-4f

// ---------------- mma / ldmatrix helpers -----------------------------------
__device__ __forceinline__ void mma16816(float* d, const uint32_t* a,
                                         const uint32_t* b) {
    asm volatile(
        "mma.sync.aligned.m16n8k16.row.col.f32.f16.f16.f32 "
        "{%0,%1,%2,%3}, {%4,%5,%6,%7}, {%8,%9}, {%0,%1,%2,%3};"
        : "+f"(d[0]), "+f"(d[1]), "+f"(d[2]), "+f"(d[3])
        : "r"(a[0]), "r"(a[1]), "r"(a[2]), "r"(a[3]), "r"(b[0]), "r"(b[1]));
}
#define LDSM_X4(r, addr) \
    asm volatile("ldmatrix.sync.aligned.m8n8.x4.shared.b16 {%0,%1,%2,%3}, [%4];" \
        : "=r"((r)[0]), "=r"((r)[1]), "=r"((r)[2]), "=r"((r)[3]) : "r"(addr))
#define LDSM_X2(r, addr) \
    asm volatile("ldmatrix.sync.aligned.m8n8.x2.shared.b16 {%0,%1}, [%2];" \
        : "=r"((r)[0]), "=r"((r)[1]) : "r"(addr))

__device__ __forceinline__ uint32_t smem_u32(const void* p) {
    uint32_t a;
    asm("{ .reg .u64 t; cvta.to.shared.u64 t, %1; cvt.u32.u64 %0, t; }"
        : "=r"(a) : "l"(p));
    return a;
}

// ---------------- dummy kernels (ncu capture-slot steering) ----------------
__global__ void k_dummy1() { if (threadIdx.x < 64) g_losspart[threadIdx.x] = 0.f; }
__global__ void k_dummy2() { if (threadIdx.x < 64) g_snorm[threadIdx.x] = 0.f; }

// ---------------- kernel: codebook row norms -------------------------------
__global__ void k_prep(const float* __restrict__ cb) {
    int w = threadIdx.x >> 5, lane = threadIdx.x & 31;
    for (int rr = 0; rr < 32; rr++) {
        int k = w * 32 + rr;
        float v0 = cb[k * DCH + lane];
        float s  = __fmul_rn(v0, v0);
#pragma unroll
        for (int j = 1; j < 4; j++) {
            float v = cb[k * DCH + j * 32 + lane];
            s = __fadd_rn(s, __fmul_rn(v, v));
        }
#pragma unroll
        for (int o = 16; o; o >>= 1)
            s = __fadd_rn(s, __shfl_xor_sync(0xffffffffu, s, o));
        if (lane == 0) g_cnorm[k] = s;
    }
}

// ---------------- kernel: fp16 HMMA distance + candidates + exact re-rank --
__global__ void __launch_bounds__(512, 1)
k_gemm_mma(const float* __restrict__ z, const float* __restrict__ cb,
           float* __restrict__ out) {
    extern __shared__ float sm[];
    char* smc = (char*)sm;
    const uint32_t sbase = smem_u32(sm);

    float* scn   = sm + SCN_F;
    float* szn   = sm + SZN_F;
    float* minq  = sm + MINQ_F;
    float* srmin = sm + SRMIN_F;
    int*   ccnt  = (int*)(sm + CCNT_I);
    int*   candk = (int*)(sm + CANDK_I);
    int*   sidx  = (int*)(sm + SIDX_I);
    float* sd    = sm + SD_F;
    __shared__ float red[16];

    const int tid    = threadIdx.x;
    const int w      = tid >> 5;
    const int l      = tid & 31;
    const int tileId = blockIdx.x;
    const int b      = tileId >> 3;
    const int hw0    = (tileId & 7) << 7;
    const int n0     = tileId * TILE;

    if (tid < 256) scn[tid] = g_cnorm[tid];
    if (tid < 128) ccnt[tid] = 0;

    // ---- stage z fp16 [n][c-pair], coalesced global reads ----
    const float* zb = z + (b * DCH) * HW + hw0;
    {
        uint32_t* zf = (uint32_t*)(smc + ZF_B);   // stride 68 words
#pragma unroll
        for (int it = 0; it < 16; it++) {
            int id = it * 512 + tid;
            int n  = id & 127, p = id >> 7, c = p * 2;
            float f0 = zb[c * HW + n], f1 = zb[(c + 1) * HW + n];
            __half h0 = __float2half_rn(f0);
            __half h1 = __float2half_rn(f1);
            zf[n * 68 + p] = (uint32_t)__half_as_ushort(h0) |
                             ((uint32_t)__half_as_ushort(h1) << 16);
        }
    }
    // ---- stage codebook fp16 [k][c-pair], coalesced (256*64 = 16384 words)
    {
        uint32_t* cf = (uint32_t*)(smc + CF_B);
#pragma unroll
        for (int it = 0; it < 32; it++) {
            int id = it * 512 + tid;
            int p  = id & 63, k = id >> 6;
            float2 f = *(const float2*)(cb + k * DCH + p * 2);
            __half h0 = __float2half_rn(f.x);
            __half h1 = __float2half_rn(f.y);
            cf[k * 68 + p] = (uint32_t)__half_as_ushort(h0) |
                             ((uint32_t)__half_as_ushort(h1) << 16);
        }
    }
    __syncthreads();

    // ---- HMMA mainloop: single term z_f16 * c_f16 (ldmatrix fragments) ----
    const int mg = w & 3, q = w >> 2;
    const int mbase = mg * 32, nbase = q * 64;
    const int r4 = l >> 2, c4 = l & 3;

    float acc[64];
#pragma unroll
    for (int i = 0; i < 64; i++) acc[i] = 0.f;

    {
        const int m_local = (l & 7) + ((l >> 3) & 1) * 8;
        const int ka8 = (l >> 4) * 8;          // x4 A: lanes16-31 -> k+8 tiles
        const int kb8 = ((l >> 3) & 1) * 8;    // x2 B: lanes 8-15 -> k+8 tile
        uint32_t aAddr0 = sbase + ZF_B + (mbase + m_local) * 272 + ka8 * 2;
        uint32_t aAddr1 = aAddr0 + 16 * 272;
        uint32_t bAddr  = sbase + CF_B + (nbase + (l & 7)) * 272 + kb8 * 2;

#pragma unroll
        for (int kt = 0; kt < 8; kt++) {
            uint32_t a0[4], a1[4];
            LDSM_X4(a0, aAddr0 + kt * 32);
            LDSM_X4(a1, aAddr1 + kt * 32);
#pragma unroll
            for (int nt = 0; nt < 8; nt++) {
                uint32_t bh[2];
                LDSM_X2(bh, bAddr + nt * 8 * 272 + kt * 32);
                mma16816(acc + nt * 4,      a0, bh);
                mma16816(acc + 32 + nt * 4, a1, bh);
            }
        }
    }

    // ---- pass 1: per-row min of approx distance ----
#pragma unroll
    for (int s = 0; s < 4; s++) {
        int mt = s >> 1, hf = s & 1;
        float m = 3.4e38f;
#pragma unroll
        for (int nt = 0; nt < 8; nt++)
#pragma unroll
            for (int j = 0; j < 2; j++) {
                int k = nbase + nt * 8 + c4 * 2 + j;
                float d = scn[k] - 2.f * acc[mt*32 + nt*4 + hf*2 + j];
                m = fminf(m, d);
            }
        m = fminf(m, __shfl_xor_sync(0xffffffffu, m, 1));
        m = fminf(m, __shfl_xor_sync(0xffffffffu, m, 2));
        if (c4 == 0) {
            int row = mbase + mt * 16 + hf * 8 + r4;
            minq[row * 4 + q] = m;
        }
    }
    __syncthreads();
    if (tid < 128)
        srmin[tid] = fminf(fminf(minq[tid*4], minq[tid*4+1]),
                           fminf(minq[tid*4+2], minq[tid*4+3]));
    __syncthreads();

    // ---- pass 2: collect candidates within margin ----
#pragma unroll
    for (int s = 0; s < 4; s++) {
        int mt = s >> 1, hf = s & 1;
        int row = mbase + mt * 16 + hf * 8 + r4;
        float thr = srmin[row] + MARGIN;
#pragma unroll
        for (int nt = 0; nt < 8; nt++)
#pragma unroll
            for (int j = 0; j < 2; j++) {
                int k = nbase + nt * 8 + c4 * 2 + j;
                float d = scn[k] - 2.f * acc[mt*32 + nt*4 + hf*2 + j];
                if (d <= thr) {
                    int p = atomicAdd(&ccnt[row], 1);
                    if (p < 12) candk[row * 12 + p] = k;
                }
            }
    }
    __syncthreads();

    // ---- restage fp32 zt / cbt (aliases fp16 regions) ----
    float* zt  = sm;              // [128 c][129]
    float* cbt = sm + CBT_F;      // [128 c][257]
    for (int i = tid; i < TILE * DCH; i += 512) {
        int c = i >> 7, n = i & 127;
        zt[c * 129 + n] = zb[c * HW + n];
    }
    for (int i = tid; i < KCODE * DCH; i += 512) {
        int k = i >> 7, c = i & 127;
        cbt[c * 257 + k] = cb[k * DCH + c];
    }
    __syncthreads();

    // ---- znorm per row (XLA pattern, identical rounding) ----
    for (int r = 0; r < 8; r++) {
        int n = w * 8 + r;
        float v0 = zt[l * 129 + n];
        float a  = __fmul_rn(v0, v0);
#pragma unroll
        for (int j = 1; j < 4; j++) {
            float v = zt[(l + 32 * j) * 129 + n];
            a = __fadd_rn(a, __fmul_rn(v, v));
        }
#pragma unroll
        for (int o = 16; o; o >>= 1)
            a = __fadd_rn(a, __shfl_xor_sync(0xffffffffu, a, o));
        if (l == 0) szn[n] = a;
    }
    __syncthreads();

    // ---- exact re-rank: one candidate per thread (reference-rounded) ----
    {
        int row = tid >> 2, j = tid & 3;
        int cn = min(ccnt[row], 12);
        float d = 3.4e38f;
        if (j < cn) {
            int k = candk[row * 12 + j];
            float a = 0.f;
            const float* cr = cbt + k;
#pragma unroll 8
            for (int c = 0; c < DCH; c++)
                a = __fmaf_rn(zt[c * 129 + row], cr[c * 257], a);
            d = __fadd_rn(__fadd_rn(szn[row], -__fmul_rn(2.f, a)), scn[k]);
        }
        sd[row * 12 + j] = d;
#pragma unroll
        for (int it = 0; it < 2; it++) {
            int id = it * 512 + tid;
            int row2 = id >> 3, j2 = 4 + (id & 7);
            int cn2 = min(ccnt[row2], 12);
            float d2 = 3.4e38f;
            if (j2 < cn2) {
                int k = candk[row2 * 12 + j2];
                float a = 0.f;
                const float* cr = cbt + k;
#pragma unroll 8
                for (int c = 0; c < DCH; c++)
                    a = __fmaf_rn(zt[c * 129 + row2], cr[c * 257], a);
                d2 = __fadd_rn(__fadd_rn(szn[row2], -__fmul_rn(2.f, a)), scn[k]);
            }
            sd[row2 * 12 + j2] = d2;
        }
    }
    __syncthreads();

    // ---- per-row (d, k) min reduce ----
    for (int i = 0; i < 8; i++) {
        int row = w * 8 + i;
        float d = (l < 12) ? sd[row * 12 + l] : 3.4e38f;
        int   k = (l < 12) ? candk[row * 12 + l] : 0x7fffffff;
        if (d >= 3.4e38f) k = 0x7fffffff;
#pragma unroll
        for (int off = 16; off; off >>= 1) {
            float ov = __shfl_xor_sync(0xffffffffu, d, off);
            int   ok = __shfl_xor_sync(0xffffffffu, k, off);
            if (ov < d || (ov == d && ok < k)) { d = ov; k = ok; }
        }
        if (l == 0) {
            sidx[row] = k;
            g_idx[n0 + row] = k;
            out[IDX_OFF + n0 + row] = (float)k;
        }
    }
    __syncthreads();

    // ---- quantize (straight-through) + loss ----
    float lsum = 0.f;
    float* outq = out + Q_OFF + (b * DCH) * HW + hw0;
#pragma unroll 4
    for (int it = 0; it < 32; it++) {
        int e = it * 512 + tid;
        int c = e >> 7, n = e & 127;
        int k = sidx[n];
        float zv = zt[c * 129 + n];
        float qv = cbt[c * 257 + k];
        float d  = __fadd_rn(qv, -zv);
        outq[c * HW + n] = __fadd_rn(zv, d);
        lsum += d * d;
    }
#pragma unroll
    for (int off = 16; off; off >>= 1)
        lsum += __shfl_xor_sync(0xffffffffu, lsum, off);
    if (l == 0) red[w] = lsum;
    __syncthreads();
    if (tid == 0) {
        float t = 0.f;
        for (int i = 0; i < 16; i++) t += red[i];
        g_losspart[blockIdx.x] = t;
    }
}

// ---------------- kernel: per-batch enc_batch via staged SMEM --------------
#define CHUNK 64
__global__ void __launch_bounds__(512, 1)
k_encbatch(const float* __restrict__ z) {
    extern __shared__ float sm[];
    float* sacc  = sm;                              // [256][128]
    float* zs    = sm + KCODE * DCH;                // [128][65]
    int*   ssidx = (int*)(zs + 128 * 65);           // [1024]
    int*   scnt  = ssidx + HW;                      // [256]
    const int tid = threadIdx.x, b = blockIdx.x;

    for (int i = tid; i < KCODE * DCH; i += 512) sacc[i] = 0.f;
    if (tid < 256) scnt[tid] = 0;
    for (int i = tid; i < HW; i += 512) ssidx[i] = g_idx[b * HW + i];

    const int ks = tid >> 7, c = tid & 127;
    const float* zb = z + (b * DCH) * HW;

    for (int ch = 0; ch < HW / CHUNK; ch++) {
        const int r0 = ch * CHUNK;
        __syncthreads();
        for (int i = tid; i < DCH * CHUNK; i += 512) {
            int cc = i >> 6, r = i & (CHUNK - 1);
            zs[cc * (CHUNK + 1) + r] = zb[cc * HW + r0 + r];
        }
        __syncthreads();
#pragma unroll 4
        for (int r = 0; r < CHUNK; r++) {
            int k = ssidx[r0 + r];
            if ((k & 3) == ks) {
                sacc[k * DCH + c] += zs[c * (CHUNK + 1) + r];
                if (c == 0) scnt[k]++;
            }
        }
    }
    __syncthreads();
    for (int i = tid; i < KCODE * DCH; i += 512)
        g_part[b * (KCODE * DCH) + i] = sacc[i];
    if (tid < 256) g_cntpart[b * KCODE + tid] = (float)scnt[tid];
}

// ---------------- batch reduction ------------------------------------------
__global__ void k_reduceA() {
    int bg = blockIdx.x >> 8;
    int k  = blockIdx.x & 255;
    int c  = threadIdx.x;
    const float* p = g_part + (bg * 16) * (KCODE * DCH) + k * DCH + c;
    float s = 0.f;
#pragma unroll
    for (int bi = 0; bi < 16; bi++) s += p[bi * (KCODE * DCH)];
    g_part2[bg * (KCODE * DCH) + k * DCH + c] = s;
}
__global__ void k_reduceB(const float* __restrict__ emaw,
                          float* __restrict__ out) {
    int k = blockIdx.x, c = threadIdx.x;
    float s = 0.f;
#pragma unroll
    for (int bg = 0; bg < 8; bg++) s += g_part2[bg * (KCODE * DCH) + k * DCH + c];
    int i = k * DCH + c;
    out[NW_OFF + i] = __fadd_rn(__fmul_rn(0.99f, emaw[i]), __fmul_rn(0.01f, s));
}

// ---------------- counts, losses, snorm ------------------------------------
__global__ void k_final(const float* __restrict__ emac, float* __restrict__ out) {
    __shared__ float snc[256], sred[256];
    __shared__ float s_n;
    const int t = threadIdx.x;

    float cs = 0.f;
#pragma unroll 8
    for (int b = 0; b < BATCH; b++) cs += g_cntpart[b * KCODE + t];
    float nc = __fadd_rn(__fmul_rn(0.99f, emac[t]), __fmul_rn(0.01f, cs));
    out[CNT_OFF + t] = nc;
    snc[t] = nc;

    float lp = 0.f;
    for (int i = t; i < NTILES; i += 256) lp += g_losspart[i];
    sred[t] = lp;
    __syncthreads();

    if (t == 0) {
        float n = 0.f;
        for (int i = 0; i < 256; i++) n += snc[i];
        s_n = n;
        float L = 0.f;
        for (int i = 0; i < 256; i++) L += sred[i];
        L /= 16777216.0f;
        out[COMMIT_OFF] = 0.25f * L;
        out[CBL_OFF]    = L;
    }
    __syncthreads();

    float n = s_n;
    g_snorm[t] = __fmul_rn(__fdiv_rn(__fadd_rn(snc[t], 1e-5f),
                                     __fadd_rn(n, 256.0f * 1e-5f)), n);
}

// ---------------- new_codebook ---------------------------------------------
__global__ void k_ncb(float* __restrict__ out) {
    int k = blockIdx.x, c = threadIdx.x;
    int i = k * DCH + c;
    out[NCB_OFF + i] = __fdiv_rn(out[NW_OFF + i], g_snorm[k]);
}

// ---------------- launch ---------------------------------------------------
extern "C" void kernel_launch(void* const* d_in, const int* in_sizes, int n_in,
                              void* d_out, int out_size) {
    const float* z    = (const float*)d_in[0];
    const float* cb   = (const float*)d_in[1];
    const float* emac = (const float*)d_in[2];
    const float* emaw = (const float*)d_in[3];
    float* out = (float*)d_out;

    const int ENC_SMEM = (KCODE * DCH + 128 * 65) * 4 + (HW + KCODE) * 4;
    cudaFuncSetAttribute(k_gemm_mma, cudaFuncAttributeMaxDynamicSharedMemorySize,
                         SMEM_TC);
    cudaFuncSetAttribute(k_encbatch, cudaFuncAttributeMaxDynamicSharedMemorySize,
                         ENC_SMEM);

    k_prep<<<1, 256>>>(cb);          // launch 0
    k_dummy1<<<1, 64>>>();           // launch 1
    k_dummy2<<<1, 64>>>();           // launch 2
    k_gemm_mma<<<NTILES, 512, SMEM_TC>>>(z, cb, out);   // launch 3 (ncu slot)
    k_encbatch<<<BATCH, 512, ENC_SMEM>>>(z);
    k_reduceA<<<2048, 128>>>();
    k_reduceB<<<KCODE, DCH>>>(emaw, out);
    k_final<<<1, 256>>>(emac, out);
    k_ncb<<<KCODE, DCH>>>(out);
}